// round 2
// baseline (speedup 1.0000x reference)
#include <cuda_runtime.h>
#include <cstdint>

#define N_NODES 100000
#define E_EDGES 3200000
#define NFEAT   512
#define NHID    256
#define NCLASS  64
#define K_HOPS  10

// ---------------- scratch (device globals; no allocation allowed) ----------------
__device__ float g_h1[(size_t)N_NODES * NHID];     // MLP hidden   (102.4 MB)
__device__ float g_hA[(size_t)N_NODES * NCLASS];   // ping         (25.6 MB)
__device__ float g_hB[(size_t)N_NODES * NCLASS];   // pong         (25.6 MB)
__device__ float g_hidden[(size_t)N_NODES * NCLASS];
__device__ float g_dinv[N_NODES];
__device__ int   g_deg[N_NODES];
__device__ int   g_cursor[N_NODES];
__device__ int   g_rowptr[N_NODES + 1];
__device__ int   g_col[E_EDGES];
__device__ float g_wgt[E_EDGES];

// ---------------- small utility kernels ----------------
__global__ void zero2_kernel(int n) {
    int i = blockIdx.x * blockDim.x + threadIdx.x;
    if (i < n) { g_deg[i] = 0; g_cursor[i] = 0; }
}

__global__ void deg_kernel(const int* __restrict__ ei) {
    int e = blockIdx.x * blockDim.x + threadIdx.x;
    if (e < E_EDGES) {
        int d = ei[(size_t)E_EDGES + e];   // row 1 = dst
        atomicAdd(&g_deg[d], 1);
    }
}

__global__ void dinv_kernel(int n) {
    int i = blockIdx.x * blockDim.x + threadIdx.x;
    if (i < n) {
        // +1 for self loop; deg >= 1 always
        g_dinv[i] = rsqrtf((float)(g_deg[i] + 1));
    }
}

// single-block exclusive scan of g_deg -> g_rowptr (n = 100000)
__global__ void scan_kernel(int n) {
    __shared__ int tmp[1024];
    __shared__ int carry;
    int tid = threadIdx.x;
    if (tid == 0) carry = 0;
    __syncthreads();
    for (int base = 0; base < n; base += 1024) {
        int i = base + tid;
        int v = (i < n) ? g_deg[i] : 0;
        tmp[tid] = v;
        __syncthreads();
        #pragma unroll
        for (int off = 1; off < 1024; off <<= 1) {
            int t = (tid >= off) ? tmp[tid - off] : 0;
            __syncthreads();
            tmp[tid] += t;
            __syncthreads();
        }
        int incl = tmp[tid];
        int c = carry;
        if (i < n) g_rowptr[i] = c + incl - v;
        __syncthreads();
        if (tid == 0) carry = c + tmp[1023];
        __syncthreads();
    }
    if (threadIdx.x == 0) g_rowptr[n] = carry;
}

__global__ void build_kernel(const int* __restrict__ ei) {
    int e = blockIdx.x * blockDim.x + threadIdx.x;
    if (e < E_EDGES) {
        int s = ei[e];                       // row 0 = src
        int d = ei[(size_t)E_EDGES + e];     // row 1 = dst
        float w = g_dinv[s] * g_dinv[d];
        int pos = atomicAdd(&g_cursor[d], 1);
        int idx = g_rowptr[d] + pos;
        g_col[idx] = s;
        g_wgt[idx] = w;
    }
}

// ---------------- SIMT fp32 GEMM: C[M,N] = A[M,K]*B[K,N] + bias (opt relu) ------
// BM=128, BN=64, BK=16, 256 threads, thread tile 8x4
template <bool RELU>
__global__ __launch_bounds__(256) void gemm_kernel(
    const float* __restrict__ A, const float* __restrict__ B,
    const float* __restrict__ bias, float* __restrict__ C,
    int M, int N, int K)
{
    const int BM = 128, BN = 64, BK = 16, TM = 8, TN = 4;
    __shared__ float As[BK][BM];   // transposed
    __shared__ float Bs[BK][BN];

    int tid = threadIdx.x;
    int tx = tid & 15;   // 16 col-groups * TN=4 -> 64
    int ty = tid >> 4;   // 16 row-groups * TM=8 -> 128
    int blockRow = blockIdx.x * BM;
    int blockCol = blockIdx.y * BN;

    int aRow = tid >> 2;         // 0..63
    int aCol = (tid & 3) << 2;   // 0,4,8,12
    int bRow = tid >> 4;         // 0..15
    int bCol = (tid & 15) << 2;  // 0..60

    float acc[TM][TN] = {};

    for (int k0 = 0; k0 < K; k0 += BK) {
        #pragma unroll
        for (int r = 0; r < 2; r++) {
            int row = blockRow + aRow + r * 64;
            float4 v = make_float4(0.f, 0.f, 0.f, 0.f);
            if (row < M) v = *(const float4*)&A[(size_t)row * K + k0 + aCol];
            As[aCol + 0][aRow + r * 64] = v.x;
            As[aCol + 1][aRow + r * 64] = v.y;
            As[aCol + 2][aRow + r * 64] = v.z;
            As[aCol + 3][aRow + r * 64] = v.w;
        }
        {
            float4 v = *(const float4*)&B[(size_t)(k0 + bRow) * N + blockCol + bCol];
            *(float4*)&Bs[bRow][bCol] = v;
        }
        __syncthreads();
        #pragma unroll
        for (int kk = 0; kk < BK; kk++) {
            float a[TM], b[TN];
            float4 a0 = *(const float4*)&As[kk][ty * TM];
            float4 a1 = *(const float4*)&As[kk][ty * TM + 4];
            a[0] = a0.x; a[1] = a0.y; a[2] = a0.z; a[3] = a0.w;
            a[4] = a1.x; a[5] = a1.y; a[6] = a1.z; a[7] = a1.w;
            float4 b0 = *(const float4*)&Bs[kk][tx * TN];
            b[0] = b0.x; b[1] = b0.y; b[2] = b0.z; b[3] = b0.w;
            #pragma unroll
            for (int i = 0; i < TM; i++)
                #pragma unroll
                for (int j = 0; j < TN; j++)
                    acc[i][j] += a[i] * b[j];
        }
        __syncthreads();
    }

    float4 bv = *(const float4*)&bias[blockCol + tx * TN];
    #pragma unroll
    for (int i = 0; i < TM; i++) {
        int row = blockRow + ty * TM + i;
        if (row < M) {
            float4 o;
            o.x = acc[i][0] + bv.x;
            o.y = acc[i][1] + bv.y;
            o.z = acc[i][2] + bv.z;
            o.w = acc[i][3] + bv.w;
            if (RELU) {
                o.x = fmaxf(o.x, 0.f); o.y = fmaxf(o.y, 0.f);
                o.z = fmaxf(o.z, 0.f); o.w = fmaxf(o.w, 0.f);
            }
            *(float4*)&C[(size_t)row * N + blockCol + tx * TN] = o;
        }
    }
}

// ---------------- hidden = temp[0]*h ----------------
__global__ void scale_kernel(const float* __restrict__ h,
                             const float* __restrict__ temp) {
    int i = blockIdx.x * blockDim.x + threadIdx.x;
    if (i < N_NODES * NCLASS) g_hidden[i] = temp[0] * h[i];
}

// ---------------- one propagation hop (warp per dst node, float2/lane) ----------
__global__ __launch_bounds__(256) void propagate_kernel(
    const float* __restrict__ hin, float* __restrict__ hout,
    const float* __restrict__ temp, int kidx)
{
    int warp = (blockIdx.x * blockDim.x + threadIdx.x) >> 5;
    int lane = threadIdx.x & 31;
    if (warp >= N_NODES) return;

    const float2* hin2 = (const float2*)hin;
    float di = g_dinv[warp];
    float2 hv = __ldg(&hin2[(size_t)warp * 32 + lane]);
    float sw = di * di;      // self-loop weight
    float accx = sw * hv.x, accy = sw * hv.y;

    int beg = g_rowptr[warp];
    int end = g_rowptr[warp + 1];
    for (int e = beg; e < end; e++) {
        int s   = __ldg(&g_col[e]);
        float w = __ldg(&g_wgt[e]);
        float2 v = __ldg(&hin2[(size_t)s * 32 + lane]);
        accx += w * v.x;
        accy += w * v.y;
    }

    float tk = temp[kidx];
    ((float2*)hout)[(size_t)warp * 32 + lane] = make_float2(accx, accy);
    float2* hid2 = (float2*)g_hidden;
    float2 h = hid2[(size_t)warp * 32 + lane];
    h.x += tk * accx;
    h.y += tk * accy;
    hid2[(size_t)warp * 32 + lane] = h;
}

// ---------------- log_softmax over 64 classes (warp per row) ----------------
__global__ void logsoftmax_kernel(float* __restrict__ out) {
    int warp = (blockIdx.x * blockDim.x + threadIdx.x) >> 5;
    int lane = threadIdx.x & 31;
    if (warp >= N_NODES) return;
    float2 v = ((const float2*)g_hidden)[(size_t)warp * 32 + lane];
    float m = fmaxf(v.x, v.y);
    #pragma unroll
    for (int o = 16; o; o >>= 1) m = fmaxf(m, __shfl_xor_sync(0xffffffffu, m, o));
    float s = expf(v.x - m) + expf(v.y - m);
    #pragma unroll
    for (int o = 16; o; o >>= 1) s += __shfl_xor_sync(0xffffffffu, s, o);
    float lse = m + logf(s);
    ((float2*)out)[(size_t)warp * 32 + lane] = make_float2(v.x - lse, v.y - lse);
}

// ---------------- launch ----------------
extern "C" void kernel_launch(void* const* d_in, const int* in_sizes, int n_in,
                              void* d_out, int out_size) {
    const float* x    = (const float*)d_in[0];
    const int*   ei   = (const int*)d_in[1];    // int32 (JAX x64 disabled)
    const float* W1   = (const float*)d_in[2];
    const float* b1   = (const float*)d_in[3];
    const float* W2   = (const float*)d_in[4];
    const float* b2   = (const float*)d_in[5];
    const float* temp = (const float*)d_in[6];
    float*       out  = (float*)d_out;

    float *h1, *hA, *hB;
    cudaGetSymbolAddress((void**)&h1, g_h1);
    cudaGetSymbolAddress((void**)&hA, g_hA);
    cudaGetSymbolAddress((void**)&hB, g_hB);

    // graph structure: degrees, norms, CSR by dst
    zero2_kernel<<<(N_NODES + 255) / 256, 256>>>(N_NODES);
    deg_kernel<<<(E_EDGES + 255) / 256, 256>>>(ei);
    dinv_kernel<<<(N_NODES + 255) / 256, 256>>>(N_NODES);
    scan_kernel<<<1, 1024>>>(N_NODES);
    build_kernel<<<(E_EDGES + 255) / 256, 256>>>(ei);

    // MLP
    {
        dim3 grid((N_NODES + 127) / 128, NHID / 64);
        gemm_kernel<true><<<grid, 256>>>(x, W1, b1, h1, N_NODES, NHID, NFEAT);
    }
    {
        dim3 grid((N_NODES + 127) / 128, NCLASS / 64);
        gemm_kernel<false><<<grid, 256>>>(h1, W2, b2, hA, N_NODES, NCLASS, NHID);
    }

    // hidden = temp[0] * h
    scale_kernel<<<(N_NODES * NCLASS + 255) / 256, 256>>>(hA, temp);

    // propagation: 10 hops, ping-pong hA/hB
    for (int k = 0; k < K_HOPS; k++) {
        const float* hin = (k & 1) ? hB : hA;
        float*       ho  = (k & 1) ? hA : hB;
        propagate_kernel<<<(N_NODES + 7) / 8, 256>>>(hin, ho, temp, k + 1);
    }

    logsoftmax_kernel<<<(N_NODES + 7) / 8, 256>>>(out);
}